// round 1
// baseline (speedup 1.0000x reference)
#include <cuda_runtime.h>
#include <cstdint>

#define NB 256
#define NT 512
#define NI 64
#define ND 512
#define NO 128

// 256 MB scratch for e = tanh(x @ W_in^T + b_in), layout [B*T][D]
__device__ float g_e[(size_t)NB * NT * ND];

// Accurate-enough tanh: 2 MUFU + few FMA, abs error ~1e-7.
// tanh(x) = 1 - 2*exp(-2x) / (1 + exp(-2x)); clamp keeps exp finite.
__device__ __forceinline__ float tanh_fast(float x) {
    x = fminf(20.0f, fmaxf(-20.0f, x));
    float t = __expf(-2.0f * x);
    return 1.0f - __fdividef(2.0f * t, 1.0f + t);
}

// Packed dual-fp32 FMA (B300 f32x2 pipe): d = a*b + d on 2 lanes.
__device__ __forceinline__ void ffma2(unsigned long long& d,
                                      unsigned long long a,
                                      unsigned long long b) {
    asm("fma.rn.f32x2 %0, %1, %2, %0;" : "+l"(d) : "l"(a), "l"(b));
}

__device__ __forceinline__ unsigned long long pack2(float v) {
    unsigned long long r;
    asm("mov.b64 %0, {%1, %1};" : "=l"(r) : "f"(v));
    return r;
}

__device__ __forceinline__ float2 unpack2(unsigned long long p) {
    float2 r;
    asm("mov.b64 {%0, %1}, %2;" : "=f"(r.x), "=f"(r.y) : "l"(p));
    return r;
}

// ---------------------------------------------------------------------------
// Kernel A: e[m][n] = tanh( sum_k x[m][k] * W_in[n][k] + b_in[n] )
// Block tile: 64 rows (M) x 512 cols (N), full K=64 in smem (k-major layouts).
// 512 threads, thread tile 4M x 16N, accumulators as 32 packed f32x2.
// ---------------------------------------------------------------------------
__global__ __launch_bounds__(512, 1)
void embed_kernel(const float* __restrict__ xg,
                  const float* __restrict__ Wg,
                  const float* __restrict__ bg) {
    extern __shared__ float sm[];
    float* Ws = sm;             // [64][512]  Ws[k*512 + n] = W_in[n][k]
    float* xs = sm + NI * ND;   // [64][64]   xs[k*64 + m]  = x[m0+m][k]
    const int tid = threadIdx.x;
    const int m0 = blockIdx.x * 64;

    // Load W transposed: thread tid owns W_in row n = tid (64 floats).
    {
        const float4* wr = reinterpret_cast<const float4*>(Wg + tid * NI);
        #pragma unroll
        for (int kk = 0; kk < 16; kk++) {
            float4 v = wr[kk];
            Ws[(4 * kk + 0) * ND + tid] = v.x;
            Ws[(4 * kk + 1) * ND + tid] = v.y;
            Ws[(4 * kk + 2) * ND + tid] = v.z;
            Ws[(4 * kk + 3) * ND + tid] = v.w;
        }
    }
    // Load x tile transposed: 8 threads per row, 2 float4 each.
    {
        const int r = tid >> 3;
        const int c = tid & 7;
        const float4* xr = reinterpret_cast<const float4*>(xg + (size_t)(m0 + r) * NI);
        #pragma unroll
        for (int q = 0; q < 2; q++) {
            int kk = c * 2 + q;
            float4 v = xr[kk];
            xs[(4 * kk + 0) * 64 + r] = v.x;
            xs[(4 * kk + 1) * 64 + r] = v.y;
            xs[(4 * kk + 2) * 64 + r] = v.z;
            xs[(4 * kk + 3) * 64 + r] = v.w;
        }
    }
    __syncthreads();

    const int ty = tid >> 5;  // 0..15 -> rows m = ty*4 + j (same for whole warp)
    const int tx = tid & 31;  // cols  n = tx*4 + 128*g

    unsigned long long acc[4][8];
    #pragma unroll
    for (int m = 0; m < 4; m++)
        #pragma unroll
        for (int p = 0; p < 8; p++) acc[m][p] = 0ULL;

    #pragma unroll 4
    for (int k = 0; k < NI; k++) {
        float4 xv = *reinterpret_cast<const float4*>(&xs[k * 64 + ty * 4]);  // broadcast
        unsigned long long xp0 = pack2(xv.x);
        unsigned long long xp1 = pack2(xv.y);
        unsigned long long xp2 = pack2(xv.z);
        unsigned long long xp3 = pack2(xv.w);
        #pragma unroll
        for (int g = 0; g < 4; g++) {
            // 16B conflict-free LDS.128: two packed f32x2 operands
            ulonglong2 w = *reinterpret_cast<const ulonglong2*>(&Ws[k * ND + tx * 4 + 128 * g]);
            ffma2(acc[0][2 * g], xp0, w.x); ffma2(acc[0][2 * g + 1], xp0, w.y);
            ffma2(acc[1][2 * g], xp1, w.x); ffma2(acc[1][2 * g + 1], xp1, w.y);
            ffma2(acc[2][2 * g], xp2, w.x); ffma2(acc[2][2 * g + 1], xp2, w.y);
            ffma2(acc[3][2 * g], xp3, w.x); ffma2(acc[3][2 * g + 1], xp3, w.y);
        }
    }

    #pragma unroll
    for (int g = 0; g < 4; g++) {
        const int n = tx * 4 + 128 * g;
        float4 bv = *reinterpret_cast<const float4*>(bg + n);
        #pragma unroll
        for (int m = 0; m < 4; m++) {
            float2 v01 = unpack2(acc[m][2 * g]);
            float2 v23 = unpack2(acc[m][2 * g + 1]);
            float4 r;
            r.x = tanh_fast(v01.x + bv.x);
            r.y = tanh_fast(v01.y + bv.y);
            r.z = tanh_fast(v23.x + bv.z);
            r.w = tanh_fast(v23.y + bv.w);
            *reinterpret_cast<float4*>(&g_e[(size_t)(m0 + ty * 4 + m) * ND + n]) = r;
        }
    }
}

// ---------------------------------------------------------------------------
// Kernel B: sequential recurrence + LayerNorm + fused logits epilogue.
// One block per batch row b. 128 threads x 4 contiguous d's in registers.
// e_t prefetched 3 steps ahead via cp.async ring (thread-private slots).
// One __syncthreads per step (parity-double-buffered cross-warp reduce).
// ---------------------------------------------------------------------------
__global__ __launch_bounds__(128, 2)
void recur_kernel(const float* __restrict__ gamma, const float* __restrict__ beta,
                  const float* __restrict__ Wout, const float* __restrict__ bout,
                  const float* __restrict__ csp, float* __restrict__ outp) {
    __shared__ float es[4][ND];                  // cp.async ring, 4 stages
    __shared__ __align__(16) float2 red[2][4];   // per-warp (sum, sumsq), parity-buffered
    const int tid = threadIdx.x;
    const int b = blockIdx.x;
    const int d0 = tid * 4;
    const int wid = tid >> 5;
    const int lane = tid & 31;

    const float scale = __fdividef(1.0f, 1.0f + __expf(-csp[0]));  // sigmoid
    const float4 g4 = *reinterpret_cast<const float4*>(gamma + d0);
    const float4 be4 = *reinterpret_cast<const float4*>(beta + d0);

    float s0 = 0.f, s1 = 0.f, s2 = 0.f, s3 = 0.f;
    float h0 = 0.f, h1 = 0.f, h2 = 0.f, h3 = 0.f;
    const float* eb = g_e + (size_t)b * NT * ND;

    unsigned sdst[4];
    #pragma unroll
    for (int st = 0; st < 4; st++)
        sdst[st] = (unsigned)__cvta_generic_to_shared(&es[st][d0]);

    #pragma unroll
    for (int t = 0; t < 3; t++) {
        asm volatile("cp.async.ca.shared.global [%0], [%1], 16;"
                     :: "r"(sdst[t]), "l"(eb + (size_t)t * ND + d0));
        asm volatile("cp.async.commit_group;");
    }

    for (int t = 0; t < NT; t++) {
        const int tp = t + 3;
        if (tp < NT)
            asm volatile("cp.async.ca.shared.global [%0], [%1], 16;"
                         :: "r"(sdst[tp & 3]), "l"(eb + (size_t)tp * ND + d0));
        asm volatile("cp.async.commit_group;");   // one group per iter, uniform count
        asm volatile("cp.async.wait_group 3;");   // stage t is now resident

        float4 e4 = *reinterpret_cast<const float4*>(&es[t & 3][d0]);
        s0 = tanh_fast(fmaf(scale, s0, e4.x) + h0);
        s1 = tanh_fast(fmaf(scale, s1, e4.y) + h1);
        s2 = tanh_fast(fmaf(scale, s2, e4.z) + h2);
        s3 = tanh_fast(fmaf(scale, s3, e4.w) + h3);

        float sum = (s0 + s1) + (s2 + s3);
        float ssq = fmaf(s0, s0, s1 * s1) + fmaf(s2, s2, s3 * s3);
        #pragma unroll
        for (int m = 16; m >= 1; m >>= 1) {
            sum += __shfl_xor_sync(0xffffffffu, sum, m);
            ssq += __shfl_xor_sync(0xffffffffu, ssq, m);
        }
        if (lane == 0) red[t & 1][wid] = make_float2(sum, ssq);
        __syncthreads();
        float4 ra = *reinterpret_cast<const float4*>(&red[t & 1][0]);
        float4 rb = *reinterpret_cast<const float4*>(&red[t & 1][2]);
        float tsum = (ra.x + ra.z) + (rb.x + rb.z);
        float tssq = (ra.y + ra.w) + (rb.y + rb.w);
        float mean = tsum * (1.0f / ND);
        float var = fmaf(mean, -mean, tssq * (1.0f / ND));
        float rs = rsqrtf(var + 1e-5f);
        h0 = fmaf((s0 - mean) * rs, g4.x, be4.x);
        h1 = fmaf((s1 - mean) * rs, g4.y, be4.y);
        h2 = fmaf((s2 - mean) * rs, g4.z, be4.z);
        h3 = fmaf((s3 - mean) * rs, g4.w, be4.w);
    }

    // ---- fused logits: out[b][o] = b_out[o] + sum_d h[d] * W_out[o][d] ----
    asm volatile("cp.async.wait_group 0;");
    __syncthreads();
    *reinterpret_cast<float4*>(&es[0][d0]) = make_float4(h0, h1, h2, h3);
    __syncthreads();

    float acc = bout[tid];  // blockDim == NO == 128, thread owns output o = tid
    const float4* wr = reinterpret_cast<const float4*>(Wout + (size_t)tid * ND);
    const float4* hv = reinterpret_cast<const float4*>(&es[0][0]);
    #pragma unroll 8
    for (int q = 0; q < ND / 4; q++) {
        float4 w = __ldg(&wr[q]);
        float4 h = hv[q];
        acc = fmaf(w.x, h.x, fmaf(w.y, h.y, fmaf(w.z, h.z, fmaf(w.w, h.w, acc))));
    }
    outp[b * NO + tid] = acc;
}

// ---------------------------------------------------------------------------
extern "C" void kernel_launch(void* const* d_in, const int* in_sizes, int n_in,
                              void* d_out, int out_size) {
    const float* x     = (const float*)d_in[0];
    const float* Win   = (const float*)d_in[1];
    const float* bin   = (const float*)d_in[2];
    const float* gamma = (const float*)d_in[3];
    const float* beta  = (const float*)d_in[4];
    const float* Wout  = (const float*)d_in[5];
    const float* bout  = (const float*)d_in[6];
    const float* cs    = (const float*)d_in[7];
    float* out = (float*)d_out;

    const int smem = (NI * ND + NI * 64) * (int)sizeof(float);  // 147456 B
    cudaFuncSetAttribute(embed_kernel, cudaFuncAttributeMaxDynamicSharedMemorySize, smem);
    embed_kernel<<<(NB * NT) / 64, 512, smem>>>(x, Win, bin);
    recur_kernel<<<NB, 128>>>(gamma, beta, Wout, bout, cs, out);
}